// round 4
// baseline (speedup 1.0000x reference)
#include <cuda_runtime.h>
#include <cuda_bf16.h>
#include <math.h>

#define BB 4
#define NN 50000
#define BN 200000          // BB*NN
#define EE 600000
#define DD 128
#define DE 64

// ---- scratch: static __device__ arrays only (no cudaMalloc allowed) ----
// float4-typed so 16B alignment is guaranteed for vector LDG/STG.
__device__ float4 g_y4[(size_t)BN * 32];   // Σ alpha * x[dst]  per src (102.4 MB)
__device__ float4 g_u4[(size_t)BN * 16];   // Σ alpha * e_emb   per src (51.2 MB)
__device__ float  g_asum[BN];              // Σ alpha           per src
__device__ float  g_attsum[BN];            // Σ exp(logit)      per dst
__device__ float  g_attexp[EE];
__device__ float  g_qa[BN];
__device__ float  g_ka[BN];
__device__ float4 g_wqa4[32];
__device__ float4 g_wka4[32];
__device__ float4 g_wea4[16];
__device__ float  g_cb[1];

// Fire-and-forget global reduction: explicit .global state space, scalar.
__device__ __forceinline__ void redg(float* p, float v) {
    unsigned long long gp = (unsigned long long)__cvta_generic_to_global(p);
    asm volatile("red.global.add.f32 [%0], %1;" :: "l"(gp), "f"(v) : "memory");
}

// ---------------------------------------------------------------------------
// K0: fold Wa: wqa = Wq@Wa, wka = Wk@Wa, wea = Wew@Wa, cb = (bq+bk+bew)·Wa
// ---------------------------------------------------------------------------
__global__ void k_prep(const float* __restrict__ Wq, const float* __restrict__ Wk,
                       const float* __restrict__ Wew,
                       const float* __restrict__ bq, const float* __restrict__ bk,
                       const float* __restrict__ bew, const float* __restrict__ Wa) {
    int j = threadIdx.x;
    float aq = 0.f, ak = 0.f;
    for (int k = 0; k < DD; k++) {
        float wa = Wa[k];
        aq += Wq[j * DD + k] * wa;
        ak += Wk[j * DD + k] * wa;
    }
    ((float*)g_wqa4)[j] = aq;
    ((float*)g_wka4)[j] = ak;
    if (j < DE) {
        float ae = 0.f;
        for (int k = 0; k < DD; k++) ae += Wew[j * DD + k] * Wa[k];
        ((float*)g_wea4)[j] = ae;
    }
    if (j == 0) {
        float c = 0.f;
        for (int k = 0; k < DD; k++) c += (bq[k] + bk[k] + bew[k]) * Wa[k];
        g_cb[0] = c;
    }
}

// ---------------------------------------------------------------------------
// K_zero: zero accumulators (graph replays -> must re-zero every launch)
// ---------------------------------------------------------------------------
__global__ void k_zero() {
    size_t i = (size_t)blockIdx.x * blockDim.x + threadIdx.x;
    float4 z = make_float4(0.f, 0.f, 0.f, 0.f);
    g_y4[i] = z;                                   // grid*block == BN*32 exactly
    if (i < (size_t)BN * 16) g_u4[i] = z;
    if (i < BN) { g_asum[i] = 0.f; g_attsum[i] = 0.f; }
}

// ---------------------------------------------------------------------------
// K1: per-node scalars qa = x·wqa, ka = x·wka   (one warp per node)
// ---------------------------------------------------------------------------
__global__ __launch_bounds__(256) void k_node(const float* __restrict__ x) {
    int w = (int)((blockIdx.x * blockDim.x + threadIdx.x) >> 5);
    int lane = threadIdx.x & 31;
    if (w >= BN) return;
    float4 xv = ((const float4*)x)[(size_t)w * 32 + lane];
    float4 wq = g_wqa4[lane];
    float4 wk = g_wka4[lane];
    float pq = xv.x * wq.x + xv.y * wq.y + xv.z * wq.z + xv.w * wq.w;
    float pk = xv.x * wk.x + xv.y * wk.y + xv.z * wk.z + xv.w * wk.w;
    #pragma unroll
    for (int o = 16; o > 0; o >>= 1) {
        pq += __shfl_xor_sync(0xffffffffu, pq, o);
        pk += __shfl_xor_sync(0xffffffffu, pk, o);
    }
    if (lane == 0) { g_qa[w] = pq; g_ka[w] = pk; }
}

// ---------------------------------------------------------------------------
// K2: edge pass 1 — logit, exp, segmented denominator (4 threads per edge)
//     NOTE: edge_index / batch_index are INT32 (JAX x64 is off).
// ---------------------------------------------------------------------------
__global__ __launch_bounds__(128) void k_edge1(const int* __restrict__ ei,
                                               const int* __restrict__ bi,
                                               const float* __restrict__ e_emb) {
    int t = blockIdx.x * blockDim.x + threadIdx.x;
    int e = t >> 2;
    int sub = t & 3;
    if (e >= EE) return;
    const float4* er = (const float4*)(e_emb + (size_t)e * DE);
    float p = 0.f;
    #pragma unroll
    for (int i = 0; i < 4; i++) {
        float4 v  = er[sub * 4 + i];
        float4 wv = g_wea4[sub * 4 + i];
        p += v.x * wv.x + v.y * wv.y + v.z * wv.z + v.w * wv.w;
    }
    p += __shfl_xor_sync(0xffffffffu, p, 1);
    p += __shfl_xor_sync(0xffffffffu, p, 2);
    if (sub == 0) {
        int s = ei[e];
        int d = ei[EE + e];
        int b = bi[e];
        int gs = b * NN + s;
        int gd = b * NN + d;
        float logit = (g_qa[gs] + g_ka[gd] + p + g_cb[0]) * 0.25f;  // 1/sqrt(d_h=16)
        float ex = expf(logit);
        g_attexp[e] = ex;
        redg(&g_attsum[gd], ex);
    }
}

// ---------------------------------------------------------------------------
// K3: edge pass 2 — alpha, scatter alpha*x[dst] -> y[src], alpha*e_emb -> u[src]
//     one warp per edge; scalar red.global.add.f32, coalesced per warp
// ---------------------------------------------------------------------------
__global__ __launch_bounds__(256) void k_edge2(const int* __restrict__ ei,
                                               const int* __restrict__ bi,
                                               const float* __restrict__ e_emb,
                                               const float* __restrict__ x) {
    int e = (int)((blockIdx.x * blockDim.x + threadIdx.x) >> 5);
    int lane = threadIdx.x & 31;
    if (e >= EE) return;
    int s = ei[e];
    int d = ei[EE + e];
    int b = bi[e];
    int gs = b * NN + s;
    int gd = b * NN + d;
    float alpha = g_attexp[e] / (g_attsum[gd] + 1e-9f);

    float4 xv = ((const float4*)x)[(size_t)gd * 32 + lane];
    float* yp = (float*)g_y4 + (size_t)gs * DD + lane * 4;
    redg(yp + 0, alpha * xv.x);
    redg(yp + 1, alpha * xv.y);
    redg(yp + 2, alpha * xv.z);
    redg(yp + 3, alpha * xv.w);

    if (lane < 16) {
        float4 ev = ((const float4*)e_emb)[(size_t)e * 16 + lane];
        float* up = (float*)g_u4 + (size_t)gs * DE + lane * 4;
        redg(up + 0, alpha * ev.x);
        redg(up + 1, alpha * ev.y);
        redg(up + 2, alpha * ev.z);
        redg(up + 3, alpha * ev.w);
    }
    if (lane == 0) redg(&g_asum[gs], alpha);
}

// ---------------------------------------------------------------------------
// K4: epilogue — out[n] = y[n]@Wv + u[n]@Wev + asum[n]*(bv+bev)
//     4 nodes per 128-thread block; thread owns one output column.
// ---------------------------------------------------------------------------
__global__ __launch_bounds__(128) void k_epi(const float* __restrict__ Wv,
                                             const float* __restrict__ bv,
                                             const float* __restrict__ Wev,
                                             const float* __restrict__ bev,
                                             float* __restrict__ out) {
    __shared__ float4 ys4[4 * 32];   // 4 rows x 128 floats
    __shared__ float4 us4[4 * 16];   // 4 rows x 64 floats
    __shared__ float  as[4];
    int c = threadIdx.x;
    int n0 = blockIdx.x * 4;

    ys4[c] = g_y4[(size_t)n0 * 32 + c];
    if (c < 64) us4[c] = g_u4[(size_t)n0 * 16 + c];
    if (c < 4) as[c] = g_asum[n0 + c];
    __syncthreads();

    const float* ys = (const float*)ys4;   // ys[r*DD + j]
    const float* us = (const float*)us4;   // us[r*DE + j]

    float a0 = 0.f, a1 = 0.f, a2 = 0.f, a3 = 0.f;
    #pragma unroll 4
    for (int j = 0; j < DD; j += 4) {
        float w0 = Wv[(j + 0) * DD + c];
        float w1 = Wv[(j + 1) * DD + c];
        float w2 = Wv[(j + 2) * DD + c];
        float w3 = Wv[(j + 3) * DD + c];
        float4 y0 = *(const float4*)(ys + 0 * DD + j);
        float4 y1 = *(const float4*)(ys + 1 * DD + j);
        float4 y2 = *(const float4*)(ys + 2 * DD + j);
        float4 y3 = *(const float4*)(ys + 3 * DD + j);
        a0 += w0 * y0.x + w1 * y0.y + w2 * y0.z + w3 * y0.w;
        a1 += w0 * y1.x + w1 * y1.y + w2 * y1.z + w3 * y1.w;
        a2 += w0 * y2.x + w1 * y2.y + w2 * y2.z + w3 * y2.w;
        a3 += w0 * y3.x + w1 * y3.y + w2 * y3.z + w3 * y3.w;
    }
    #pragma unroll 4
    for (int j = 0; j < DE; j += 4) {
        float w0 = Wev[(j + 0) * DD + c];
        float w1 = Wev[(j + 1) * DD + c];
        float w2 = Wev[(j + 2) * DD + c];
        float w3 = Wev[(j + 3) * DD + c];
        float4 u0 = *(const float4*)(us + 0 * DE + j);
        float4 u1 = *(const float4*)(us + 1 * DE + j);
        float4 u2 = *(const float4*)(us + 2 * DE + j);
        float4 u3 = *(const float4*)(us + 3 * DE + j);
        a0 += w0 * u0.x + w1 * u0.y + w2 * u0.z + w3 * u0.w;
        a1 += w0 * u1.x + w1 * u1.y + w2 * u1.z + w3 * u1.w;
        a2 += w0 * u2.x + w1 * u2.y + w2 * u2.z + w3 * u2.w;
        a3 += w0 * u3.x + w1 * u3.y + w2 * u3.z + w3 * u3.w;
    }
    float bb = bv[c] + bev[c];
    out[(size_t)(n0 + 0) * DD + c] = a0 + as[0] * bb;
    out[(size_t)(n0 + 1) * DD + c] = a1 + as[1] * bb;
    out[(size_t)(n0 + 2) * DD + c] = a2 + as[2] * bb;
    out[(size_t)(n0 + 3) * DD + c] = a3 + as[3] * bb;
}

// ---------------------------------------------------------------------------
extern "C" void kernel_launch(void* const* d_in, const int* in_sizes, int n_in,
                              void* d_out, int out_size) {
    const float* x     = (const float*)d_in[0];
    const int*   ei    = (const int*)d_in[1];     // int32! (JAX x64 off)
    const float* e_emb = (const float*)d_in[2];
    const int*   bi    = (const int*)d_in[3];     // int32!

    // n_heads may or may not be materialized as an input; detect via size.
    int wb = 4;
    if (n_in >= 16 && in_sizes[4] <= 1) wb = 5;
    const float* Wq  = (const float*)d_in[wb + 0];
    const float* bq  = (const float*)d_in[wb + 1];
    const float* Wk  = (const float*)d_in[wb + 2];
    const float* bk  = (const float*)d_in[wb + 3];
    const float* Wv  = (const float*)d_in[wb + 4];
    const float* bv  = (const float*)d_in[wb + 5];
    const float* Wew = (const float*)d_in[wb + 6];
    const float* bew = (const float*)d_in[wb + 7];
    const float* Wev = (const float*)d_in[wb + 8];
    const float* bev = (const float*)d_in[wb + 9];
    const float* Wa  = (const float*)d_in[wb + 10];

    float* out = (float*)d_out;

    k_prep<<<1, 128>>>(Wq, Wk, Wew, bq, bk, bew, Wa);
    k_zero<<<(BN * 32) / 256, 256>>>();                     // 25000 blocks
    k_node<<<BN / 8, 256>>>(x);                             // 25000 blocks, warp/node
    k_edge1<<<(EE * 4) / 128, 128>>>(ei, bi, e_emb);        // 18750 blocks
    k_edge2<<<EE / 8, 256>>>(ei, bi, e_emb, x);             // 75000 blocks, warp/edge
    k_epi<<<BN / 4, 128>>>(Wv, bv, Wev, bev, out);          // 50000 blocks
    (void)out_size;
}

// round 5
// speedup vs baseline: 1.2907x; 1.2907x over previous
#include <cuda_runtime.h>
#include <cuda_bf16.h>
#include <math.h>

#define BB 4
#define NN 50000
#define BN 200000          // BB*NN
#define EE 600000
#define DD 128
#define DE 64
#define NPB 16             // nodes per epilogue block

// ---- scratch: static __device__ arrays only (no cudaMalloc allowed) ----
__device__ float4 g_y4[(size_t)BN * 32];   // Σ alpha * x[dst]  per src (102.4 MB)
__device__ float4 g_u4[(size_t)BN * 16];   // Σ alpha * e_emb   per src (51.2 MB)
__device__ float  g_asum[BN];              // Σ alpha           per src
__device__ float  g_attsum[BN];            // Σ exp(logit)      per dst
__device__ float  g_attexp[EE];
__device__ float  g_qa[BN];
__device__ float  g_ka[BN];
__device__ float4 g_wqa4[32];
__device__ float4 g_wka4[32];
__device__ float4 g_wea4[16];
__device__ float  g_cb[1];

// scalar fire-and-forget global reduction
__device__ __forceinline__ void redg(float* p, float v) {
    unsigned long long gp = (unsigned long long)__cvta_generic_to_global(p);
    asm volatile("red.global.add.f32 [%0], %1;" :: "l"(gp), "f"(v) : "memory");
}
// vector (v4) global reduction — explicit .global space, sm_90+
__device__ __forceinline__ void redg4(float* p, float a, float b, float c, float d) {
    unsigned long long gp = (unsigned long long)__cvta_generic_to_global(p);
    asm volatile("red.global.add.v4.f32 [%0], {%1,%2,%3,%4};"
                 :: "l"(gp), "f"(a), "f"(b), "f"(c), "f"(d) : "memory");
}
// packed f32x2 helpers (Blackwell)
__device__ __forceinline__ unsigned long long pk2(float x) {
    unsigned long long r;
    asm("mov.b64 %0, {%1, %1};" : "=l"(r) : "f"(x));
    return r;
}
__device__ __forceinline__ void ffma2(unsigned long long& d, unsigned long long a,
                                      unsigned long long b) {
    asm("fma.rn.f32x2 %0, %1, %2, %0;" : "+l"(d) : "l"(a), "l"(b));
}

// ---------------------------------------------------------------------------
// K0: fold Wa: wqa = Wq@Wa, wka = Wk@Wa, wea = Wew@Wa, cb = (bq+bk+bew)·Wa
// ---------------------------------------------------------------------------
__global__ void k_prep(const float* __restrict__ Wq, const float* __restrict__ Wk,
                       const float* __restrict__ Wew,
                       const float* __restrict__ bq, const float* __restrict__ bk,
                       const float* __restrict__ bew, const float* __restrict__ Wa) {
    int j = threadIdx.x;
    float aq = 0.f, ak = 0.f;
    for (int k = 0; k < DD; k++) {
        float wa = Wa[k];
        aq += Wq[j * DD + k] * wa;
        ak += Wk[j * DD + k] * wa;
    }
    ((float*)g_wqa4)[j] = aq;
    ((float*)g_wka4)[j] = ak;
    if (j < DE) {
        float ae = 0.f;
        for (int k = 0; k < DD; k++) ae += Wew[j * DD + k] * Wa[k];
        ((float*)g_wea4)[j] = ae;
    }
    if (j == 0) {
        float c = 0.f;
        for (int k = 0; k < DD; k++) c += (bq[k] + bk[k] + bew[k]) * Wa[k];
        g_cb[0] = c;
    }
}

// ---------------------------------------------------------------------------
// K_zero: zero accumulators (graph replays -> must re-zero every launch)
// ---------------------------------------------------------------------------
__global__ void k_zero() {
    size_t i = (size_t)blockIdx.x * blockDim.x + threadIdx.x;
    float4 z = make_float4(0.f, 0.f, 0.f, 0.f);
    g_y4[i] = z;                                   // grid*block == BN*32 exactly
    if (i < (size_t)BN * 16) g_u4[i] = z;
    if (i < BN) { g_asum[i] = 0.f; g_attsum[i] = 0.f; }
}

// ---------------------------------------------------------------------------
// K1: per-node scalars qa = x·wqa, ka = x·wka   (one warp per node)
// ---------------------------------------------------------------------------
__global__ __launch_bounds__(256) void k_node(const float* __restrict__ x) {
    int w = (int)((blockIdx.x * blockDim.x + threadIdx.x) >> 5);
    int lane = threadIdx.x & 31;
    if (w >= BN) return;
    float4 xv = ((const float4*)x)[(size_t)w * 32 + lane];
    float4 wq = g_wqa4[lane];
    float4 wk = g_wka4[lane];
    float pq = xv.x * wq.x + xv.y * wq.y + xv.z * wq.z + xv.w * wq.w;
    float pk = xv.x * wk.x + xv.y * wk.y + xv.z * wk.z + xv.w * wk.w;
    #pragma unroll
    for (int o = 16; o > 0; o >>= 1) {
        pq += __shfl_xor_sync(0xffffffffu, pq, o);
        pk += __shfl_xor_sync(0xffffffffu, pk, o);
    }
    if (lane == 0) { g_qa[w] = pq; g_ka[w] = pk; }
}

// ---------------------------------------------------------------------------
// K2: edge pass 1 — logit, exp, segmented denominator (4 threads per edge)
// ---------------------------------------------------------------------------
__global__ __launch_bounds__(128) void k_edge1(const int* __restrict__ ei,
                                               const int* __restrict__ bi,
                                               const float* __restrict__ e_emb) {
    int t = blockIdx.x * blockDim.x + threadIdx.x;
    int e = t >> 2;
    int sub = t & 3;
    if (e >= EE) return;
    const float4* er = (const float4*)(e_emb + (size_t)e * DE);
    float p = 0.f;
    #pragma unroll
    for (int i = 0; i < 4; i++) {
        float4 v  = er[sub * 4 + i];
        float4 wv = g_wea4[sub * 4 + i];
        p += v.x * wv.x + v.y * wv.y + v.z * wv.z + v.w * wv.w;
    }
    p += __shfl_xor_sync(0xffffffffu, p, 1);
    p += __shfl_xor_sync(0xffffffffu, p, 2);
    if (sub == 0) {
        int s = ei[e];
        int d = ei[EE + e];
        int b = bi[e];
        int gs = b * NN + s;
        int gd = b * NN + d;
        float logit = (g_qa[gs] + g_ka[gd] + p + g_cb[0]) * 0.25f;  // 1/sqrt(d_h=16)
        float ex = expf(logit);
        g_attexp[e] = ex;
        redg(&g_attsum[gd], ex);
    }
}

// ---------------------------------------------------------------------------
// K3: edge pass 2 — alpha, scatter alpha*x[dst] -> y[src], alpha*e_emb -> u[src]
//     one warp per edge; vector red.global.add.v4.f32 (3.3x fewer red ops)
// ---------------------------------------------------------------------------
__global__ __launch_bounds__(256) void k_edge2(const int* __restrict__ ei,
                                               const int* __restrict__ bi,
                                               const float* __restrict__ e_emb,
                                               const float* __restrict__ x) {
    int e = (int)((blockIdx.x * blockDim.x + threadIdx.x) >> 5);
    int lane = threadIdx.x & 31;
    if (e >= EE) return;

    int gs, gd;
    float alpha;
    if (lane == 0) {
        int s = ei[e];
        int d = ei[EE + e];
        int b = bi[e];
        gs = b * NN + s;
        gd = b * NN + d;
        alpha = g_attexp[e] / (g_attsum[gd] + 1e-9f);
    }
    gs    = __shfl_sync(0xffffffffu, gs, 0);
    gd    = __shfl_sync(0xffffffffu, gd, 0);
    alpha = __shfl_sync(0xffffffffu, alpha, 0);

    float4 xv = ((const float4*)x)[(size_t)gd * 32 + lane];
    float* yp = (float*)g_y4 + (size_t)gs * DD + lane * 4;
    redg4(yp, alpha * xv.x, alpha * xv.y, alpha * xv.z, alpha * xv.w);

    if (lane < 16) {
        float4 ev = ((const float4*)e_emb)[(size_t)e * 16 + lane];
        float* up = (float*)g_u4 + (size_t)gs * DE + lane * 4;
        redg4(up, alpha * ev.x, alpha * ev.y, alpha * ev.z, alpha * ev.w);
    }
    if (lane == 0) redg(&g_asum[gs], alpha);
}

// ---------------------------------------------------------------------------
// K4: epilogue — out[n] = y[n]@Wv + u[n]@Wev + asum[n]*(bv+bev)
//     NPB=16 nodes / 128-thread block; transposed smem tile + f32x2 FMA.
// ---------------------------------------------------------------------------
__global__ __launch_bounds__(128) void k_epi(const float* __restrict__ Wv,
                                             const float* __restrict__ bv,
                                             const float* __restrict__ Wev,
                                             const float* __restrict__ bev,
                                             float* __restrict__ out) {
    __shared__ __align__(16) float yq[(DD + DE) * NPB];  // [192][16], 12.3 KB
    __shared__ float as[NPB];
    int t = threadIdx.x;
    int n0 = blockIdx.x * NPB;

    // ---- transpose-load: thread (i = t&15 node, g = t>>4 chunk) ----
    {
        int i = t & 15, g = t >> 4;                       // g in 0..7
        const float4* yrow = g_y4 + (size_t)(n0 + i) * 32 + g * 4;  // 64B contig
        #pragma unroll
        for (int q = 0; q < 4; q++) {
            float4 v = yrow[q];
            int j = g * 16 + q * 4;
            yq[(j + 0) * NPB + i] = v.x;
            yq[(j + 1) * NPB + i] = v.y;
            yq[(j + 2) * NPB + i] = v.z;
            yq[(j + 3) * NPB + i] = v.w;
        }
        const float4* urow = g_u4 + (size_t)(n0 + i) * 16 + g * 2;  // 32B contig
        #pragma unroll
        for (int q = 0; q < 2; q++) {
            float4 v = urow[q];
            int j = DD + g * 8 + q * 4;
            yq[(j + 0) * NPB + i] = v.x;
            yq[(j + 1) * NPB + i] = v.y;
            yq[(j + 2) * NPB + i] = v.z;
            yq[(j + 3) * NPB + i] = v.w;
        }
        if (t < NPB) as[t] = g_asum[n0 + t];
    }
    __syncthreads();

    // ---- compute: thread owns output column c; 8 f32x2 accumulators ----
    int c = t;
    unsigned long long acc[8] = {0, 0, 0, 0, 0, 0, 0, 0};

    #pragma unroll 4
    for (int j = 0; j < DD; j++) {
        unsigned long long w2 = pk2(Wv[j * DD + c]);
        const ulonglong2* yr = (const ulonglong2*)(yq + j * NPB);  // broadcast
        ulonglong2 p0 = yr[0];
        ulonglong2 p1 = yr[1];
        ulonglong2 p2 = yr[2];
        ulonglong2 p3 = yr[3];
        ffma2(acc[0], p0.x, w2); ffma2(acc[1], p0.y, w2);
        ffma2(acc[2], p1.x, w2); ffma2(acc[3], p1.y, w2);
        ffma2(acc[4], p2.x, w2); ffma2(acc[5], p2.y, w2);
        ffma2(acc[6], p3.x, w2); ffma2(acc[7], p3.y, w2);
    }
    #pragma unroll 4
    for (int j = 0; j < DE; j++) {
        unsigned long long w2 = pk2(Wev[j * DD + c]);
        const ulonglong2* yr = (const ulonglong2*)(yq + (DD + j) * NPB);
        ulonglong2 p0 = yr[0];
        ulonglong2 p1 = yr[1];
        ulonglong2 p2 = yr[2];
        ulonglong2 p3 = yr[3];
        ffma2(acc[0], p0.x, w2); ffma2(acc[1], p0.y, w2);
        ffma2(acc[2], p1.x, w2); ffma2(acc[3], p1.y, w2);
        ffma2(acc[4], p2.x, w2); ffma2(acc[5], p2.y, w2);
        ffma2(acc[6], p3.x, w2); ffma2(acc[7], p3.y, w2);
    }

    float bb = bv[c] + bev[c];
    #pragma unroll
    for (int m = 0; m < 8; m++) {
        float lo, hi;
        asm("mov.b64 {%0, %1}, %2;" : "=f"(lo), "=f"(hi) : "l"(acc[m]));
        out[(size_t)(n0 + 2 * m + 0) * DD + c] = lo + as[2 * m + 0] * bb;
        out[(size_t)(n0 + 2 * m + 1) * DD + c] = hi + as[2 * m + 1] * bb;
    }
}

// ---------------------------------------------------------------------------
extern "C" void kernel_launch(void* const* d_in, const int* in_sizes, int n_in,
                              void* d_out, int out_size) {
    const float* x     = (const float*)d_in[0];
    const int*   ei    = (const int*)d_in[1];     // int32 (JAX x64 off)
    const float* e_emb = (const float*)d_in[2];
    const int*   bi    = (const int*)d_in[3];     // int32

    int wb = 4;
    if (n_in >= 16 && in_sizes[4] <= 1) wb = 5;
    const float* Wq  = (const float*)d_in[wb + 0];
    const float* bq  = (const float*)d_in[wb + 1];
    const float* Wk  = (const float*)d_in[wb + 2];
    const float* bk  = (const float*)d_in[wb + 3];
    const float* Wv  = (const float*)d_in[wb + 4];
    const float* bv  = (const float*)d_in[wb + 5];
    const float* Wew = (const float*)d_in[wb + 6];
    const float* bew = (const float*)d_in[wb + 7];
    const float* Wev = (const float*)d_in[wb + 8];
    const float* bev = (const float*)d_in[wb + 9];
    const float* Wa  = (const float*)d_in[wb + 10];

    float* out = (float*)d_out;

    k_prep<<<1, 128>>>(Wq, Wk, Wew, bq, bk, bew, Wa);
    k_zero<<<(BN * 32) / 256, 256>>>();                     // 25000 blocks
    k_node<<<BN / 8, 256>>>(x);                             // 25000 blocks
    k_edge1<<<(EE * 4) / 128, 128>>>(ei, bi, e_emb);        // 18750 blocks
    k_edge2<<<EE / 8, 256>>>(ei, bi, e_emb, x);             // 75000 blocks
    k_epi<<<BN / NPB, 128>>>(Wv, bv, Wev, bev, out);        // 12500 blocks
    (void)out_size;
}

// round 6
// speedup vs baseline: 1.3443x; 1.0415x over previous
#include <cuda_runtime.h>
#include <cuda_bf16.h>
#include <math.h>

#define BB 4
#define NN 50000
#define BN 200000          // BB*NN
#define EE 600000
#define DD 128
#define DE 64
#define NPB 16             // nodes per epilogue block
#define SCAN_B 512
#define SCAN_NBLK ((BN + SCAN_B - 1) / SCAN_B)   // 391

// ---- scratch: static __device__ arrays only ----
__device__ float4 g_y4[(size_t)BN * 32];   // Σ alpha * x[dst]  per src (102.4 MB)
__device__ float4 g_u4[(size_t)BN * 16];   // Σ alpha * e_emb   per src (51.2 MB)
__device__ float  g_asum[BN];              // Σ alpha           per src
__device__ float  g_attsum[BN];            // Σ exp(logit)      per dst
__device__ float  g_attexp[EE];
__device__ float  g_qa[BN];
__device__ float  g_ka[BN];
__device__ float4 g_wqa4[32];
__device__ float4 g_wka4[32];
__device__ float4 g_wea4[16];
__device__ float  g_cb[1];
// CSR build
__device__ unsigned g_cnt[BN];             // degree histogram (by src)
__device__ unsigned g_off[BN];             // exclusive offsets
__device__ unsigned g_cur[BN];             // scatter cursors
__device__ unsigned g_bsum[SCAN_NBLK];
__device__ unsigned g_boff[SCAN_NBLK];
__device__ int      g_gd[EE];              // sorted-by-src: dst global index
__device__ int      g_eid[EE];             // sorted-by-src: edge id
__device__ float    g_alpha[EE];           // sorted-by-src: alpha

__device__ __forceinline__ void redg(float* p, float v) {
    unsigned long long gp = (unsigned long long)__cvta_generic_to_global(p);
    asm volatile("red.global.add.f32 [%0], %1;" :: "l"(gp), "f"(v) : "memory");
}
__device__ __forceinline__ void redgu(unsigned* p, unsigned v) {
    unsigned long long gp = (unsigned long long)__cvta_generic_to_global(p);
    asm volatile("red.global.add.u32 [%0], %1;" :: "l"(gp), "r"(v) : "memory");
}
__device__ __forceinline__ unsigned long long pk2(float x) {
    unsigned long long r;
    asm("mov.b64 %0, {%1, %1};" : "=l"(r) : "f"(x));
    return r;
}
__device__ __forceinline__ void ffma2(unsigned long long& d, unsigned long long a,
                                      unsigned long long b) {
    asm("fma.rn.f32x2 %0, %1, %2, %0;" : "+l"(d) : "l"(a), "l"(b));
}

// ---------------------------------------------------------------------------
__global__ void k_prep(const float* __restrict__ Wq, const float* __restrict__ Wk,
                       const float* __restrict__ Wew,
                       const float* __restrict__ bq, const float* __restrict__ bk,
                       const float* __restrict__ bew, const float* __restrict__ Wa) {
    int j = threadIdx.x;
    float aq = 0.f, ak = 0.f;
    for (int k = 0; k < DD; k++) {
        float wa = Wa[k];
        aq += Wq[j * DD + k] * wa;
        ak += Wk[j * DD + k] * wa;
    }
    ((float*)g_wqa4)[j] = aq;
    ((float*)g_wka4)[j] = ak;
    if (j < DE) {
        float ae = 0.f;
        for (int k = 0; k < DD; k++) ae += Wew[j * DD + k] * Wa[k];
        ((float*)g_wea4)[j] = ae;
    }
    if (j == 0) {
        float c = 0.f;
        for (int k = 0; k < DD; k++) c += (bq[k] + bk[k] + bew[k]) * Wa[k];
        g_cb[0] = c;
    }
}

// zero only the small per-node arrays (y/u written fully by gather)
__global__ void k_zero_small() {
    int i = blockIdx.x * blockDim.x + threadIdx.x;
    if (i < BN) { g_attsum[i] = 0.f; g_cnt[i] = 0u; g_cur[i] = 0u; }
}

// ---------------------------------------------------------------------------
__global__ __launch_bounds__(256) void k_node(const float* __restrict__ x) {
    int w = (int)((blockIdx.x * blockDim.x + threadIdx.x) >> 5);
    int lane = threadIdx.x & 31;
    if (w >= BN) return;
    float4 xv = ((const float4*)x)[(size_t)w * 32 + lane];
    float4 wq = g_wqa4[lane];
    float4 wk = g_wka4[lane];
    float pq = xv.x * wq.x + xv.y * wq.y + xv.z * wq.z + xv.w * wq.w;
    float pk = xv.x * wk.x + xv.y * wk.y + xv.z * wk.z + xv.w * wk.w;
    #pragma unroll
    for (int o = 16; o > 0; o >>= 1) {
        pq += __shfl_xor_sync(0xffffffffu, pq, o);
        pk += __shfl_xor_sync(0xffffffffu, pk, o);
    }
    if (lane == 0) { g_qa[w] = pq; g_ka[w] = pk; }
}

// ---------------------------------------------------------------------------
// edge pass 1: logit/exp + attsum red + src-degree histogram
// ---------------------------------------------------------------------------
__global__ __launch_bounds__(128) void k_edge1(const int* __restrict__ ei,
                                               const int* __restrict__ bi,
                                               const float* __restrict__ e_emb) {
    int t = blockIdx.x * blockDim.x + threadIdx.x;
    int e = t >> 2;
    int sub = t & 3;
    if (e >= EE) return;
    const float4* er = (const float4*)(e_emb + (size_t)e * DE);
    float p = 0.f;
    #pragma unroll
    for (int i = 0; i < 4; i++) {
        float4 v  = er[sub * 4 + i];
        float4 wv = g_wea4[sub * 4 + i];
        p += v.x * wv.x + v.y * wv.y + v.z * wv.z + v.w * wv.w;
    }
    p += __shfl_xor_sync(0xffffffffu, p, 1);
    p += __shfl_xor_sync(0xffffffffu, p, 2);
    if (sub == 0) {
        int s = ei[e];
        int d = ei[EE + e];
        int b = bi[e];
        int gs = b * NN + s;
        int gd = b * NN + d;
        float logit = (g_qa[gs] + g_ka[gd] + p + g_cb[0]) * 0.25f;
        float ex = expf(logit);
        g_attexp[e] = ex;
        redg(&g_attsum[gd], ex);
        redgu(&g_cnt[gs], 1u);
    }
}

// ---------------------------------------------------------------------------
// 3-kernel exclusive scan of g_cnt -> g_off
// ---------------------------------------------------------------------------
__global__ void k_scanA() {
    __shared__ unsigned sh[SCAN_B];
    int i = blockIdx.x * SCAN_B + threadIdx.x;
    unsigned v = (i < BN) ? g_cnt[i] : 0u;
    sh[threadIdx.x] = v;
    __syncthreads();
    for (int o = 1; o < SCAN_B; o <<= 1) {
        unsigned t = (threadIdx.x >= o) ? sh[threadIdx.x - o] : 0u;
        __syncthreads();
        sh[threadIdx.x] += t;
        __syncthreads();
    }
    if (i < BN) g_off[i] = sh[threadIdx.x] - v;
    if (threadIdx.x == SCAN_B - 1) g_bsum[blockIdx.x] = sh[SCAN_B - 1];
}
__global__ void k_scanB() {
    __shared__ unsigned sh[SCAN_B];
    int i = threadIdx.x;
    unsigned v = (i < SCAN_NBLK) ? g_bsum[i] : 0u;
    sh[i] = v;
    __syncthreads();
    for (int o = 1; o < SCAN_B; o <<= 1) {
        unsigned t = (i >= o) ? sh[i - o] : 0u;
        __syncthreads();
        sh[i] += t;
        __syncthreads();
    }
    if (i < SCAN_NBLK) g_boff[i] = sh[i] - v;
}
__global__ void k_scanC() {
    int i = blockIdx.x * SCAN_B + threadIdx.x;
    if (i < BN) g_off[i] += g_boff[blockIdx.x];
}

// ---------------------------------------------------------------------------
// scatter edges into src-sorted buckets, computing alpha along the way
// ---------------------------------------------------------------------------
__global__ __launch_bounds__(256) void k_scatter(const int* __restrict__ ei,
                                                 const int* __restrict__ bi) {
    int e = blockIdx.x * blockDim.x + threadIdx.x;
    if (e >= EE) return;
    int s = ei[e];
    int d = ei[EE + e];
    int b = bi[e];
    int gs = b * NN + s;
    int gd = b * NN + d;
    float a = g_attexp[e] / (g_attsum[gd] + 1e-9f);
    unsigned pos = g_off[gs] + atomicAdd(&g_cur[gs], 1u);
    g_gd[pos]    = gd;
    g_eid[pos]   = e;
    g_alpha[pos] = a;
}

// ---------------------------------------------------------------------------
// gather: one warp per src node — accumulate in registers, write once.
// ---------------------------------------------------------------------------
__global__ __launch_bounds__(256) void k_gather(const float* __restrict__ x,
                                                const float* __restrict__ e_emb) {
    int gs = (int)((blockIdx.x * blockDim.x + threadIdx.x) >> 5);
    int lane = threadIdx.x & 31;
    if (gs >= BN) return;
    unsigned off = g_off[gs];
    unsigned deg = g_cnt[gs];

    float4 ya = make_float4(0.f, 0.f, 0.f, 0.f);
    float4 ua = make_float4(0.f, 0.f, 0.f, 0.f);
    float asum = 0.f;

    for (unsigned base = 0; base < deg; base += 32) {
        unsigned rem = deg - base;
        unsigned chunk = rem < 32u ? rem : 32u;
        // vectorized metadata prefetch: lane k owns edge base+k
        int   m_gd = 0, m_e = 0;
        float m_a = 0.f;
        if (lane < chunk) {
            unsigned p = off + base + lane;
            m_gd = g_gd[p];
            m_e  = g_eid[p];
            m_a  = g_alpha[p];
        }
        for (unsigned k = 0; k < chunk; k++) {
            int   gd = __shfl_sync(0xffffffffu, m_gd, k);
            int   e  = __shfl_sync(0xffffffffu, m_e, k);
            float a  = __shfl_sync(0xffffffffu, m_a, k);
            float4 xv = ((const float4*)x)[(size_t)gd * 32 + lane];
            ya.x += a * xv.x; ya.y += a * xv.y; ya.z += a * xv.z; ya.w += a * xv.w;
            if (lane < 16) {
                float4 ev = ((const float4*)e_emb)[(size_t)e * 16 + lane];
                ua.x += a * ev.x; ua.y += a * ev.y; ua.z += a * ev.z; ua.w += a * ev.w;
            }
            asum += a;
        }
    }
    g_y4[(size_t)gs * 32 + lane] = ya;
    if (lane < 16) g_u4[(size_t)gs * 16 + lane] = ua;
    if (lane == 0) g_asum[gs] = asum;
}

// ---------------------------------------------------------------------------
// epilogue — NPB=16 nodes / 128-thread block; transposed smem + f32x2 FMA
// ---------------------------------------------------------------------------
__global__ __launch_bounds__(128) void k_epi(const float* __restrict__ Wv,
                                             const float* __restrict__ bv,
                                             const float* __restrict__ Wev,
                                             const float* __restrict__ bev,
                                             float* __restrict__ out) {
    __shared__ __align__(16) float yq[(DD + DE) * NPB];
    __shared__ float as[NPB];
    int t = threadIdx.x;
    int n0 = blockIdx.x * NPB;

    {
        int i = t & 15, g = t >> 4;
        const float4* yrow = g_y4 + (size_t)(n0 + i) * 32 + g * 4;
        #pragma unroll
        for (int q = 0; q < 4; q++) {
            float4 v = yrow[q];
            int j = g * 16 + q * 4;
            yq[(j + 0) * NPB + i] = v.x;
            yq[(j + 1) * NPB + i] = v.y;
            yq[(j + 2) * NPB + i] = v.z;
            yq[(j + 3) * NPB + i] = v.w;
        }
        const float4* urow = g_u4 + (size_t)(n0 + i) * 16 + g * 2;
        #pragma unroll
        for (int q = 0; q < 2; q++) {
            float4 v = urow[q];
            int j = DD + g * 8 + q * 4;
            yq[(j + 0) * NPB + i] = v.x;
            yq[(j + 1) * NPB + i] = v.y;
            yq[(j + 2) * NPB + i] = v.z;
            yq[(j + 3) * NPB + i] = v.w;
        }
        if (t < NPB) as[t] = g_asum[n0 + t];
    }
    __syncthreads();

    int c = t;
    unsigned long long acc[8] = {0, 0, 0, 0, 0, 0, 0, 0};

    #pragma unroll 4
    for (int j = 0; j < DD; j++) {
        unsigned long long w2 = pk2(Wv[j * DD + c]);
        const ulonglong2* yr = (const ulonglong2*)(yq + j * NPB);
        ulonglong2 p0 = yr[0], p1 = yr[1], p2 = yr[2], p3 = yr[3];
        ffma2(acc[0], p0.x, w2); ffma2(acc[1], p0.y, w2);
        ffma2(acc[2], p1.x, w2); ffma2(acc[3], p1.y, w2);
        ffma2(acc[4], p2.x, w2); ffma2(acc[5], p2.y, w2);
        ffma2(acc[6], p3.x, w2); ffma2(acc[7], p3.y, w2);
    }
    #pragma unroll 4
    for (int j = 0; j < DE; j++) {
        unsigned long long w2 = pk2(Wev[j * DD + c]);
        const ulonglong2* yr = (const ulonglong2*)(yq + (DD + j) * NPB);
        ulonglong2 p0 = yr[0], p1 = yr[1], p2 = yr[2], p3 = yr[3];
        ffma2(acc[0], p0.x, w2); ffma2(acc[1], p0.y, w2);
        ffma2(acc[2], p1.x, w2); ffma2(acc[3], p1.y, w2);
        ffma2(acc[4], p2.x, w2); ffma2(acc[5], p2.y, w2);
        ffma2(acc[6], p3.x, w2); ffma2(acc[7], p3.y, w2);
    }

    float bb = bv[c] + bev[c];
    #pragma unroll
    for (int m = 0; m < 8; m++) {
        float lo, hi;
        asm("mov.b64 {%0, %1}, %2;" : "=f"(lo), "=f"(hi) : "l"(acc[m]));
        out[(size_t)(n0 + 2 * m + 0) * DD + c] = lo + as[2 * m + 0] * bb;
        out[(size_t)(n0 + 2 * m + 1) * DD + c] = hi + as[2 * m + 1] * bb;
    }
}

// ---------------------------------------------------------------------------
extern "C" void kernel_launch(void* const* d_in, const int* in_sizes, int n_in,
                              void* d_out, int out_size) {
    const float* x     = (const float*)d_in[0];
    const int*   ei    = (const int*)d_in[1];
    const float* e_emb = (const float*)d_in[2];
    const int*   bi    = (const int*)d_in[3];

    int wb = 4;
    if (n_in >= 16 && in_sizes[4] <= 1) wb = 5;
    const float* Wq  = (const float*)d_in[wb + 0];
    const float* bq  = (const float*)d_in[wb + 1];
    const float* Wk  = (const float*)d_in[wb + 2];
    const float* bk  = (const float*)d_in[wb + 3];
    const float* Wv  = (const float*)d_in[wb + 4];
    const float* bv  = (const float*)d_in[wb + 5];
    const float* Wew = (const float*)d_in[wb + 6];
    const float* bew = (const float*)d_in[wb + 7];
    const float* Wev = (const float*)d_in[wb + 8];
    const float* bev = (const float*)d_in[wb + 9];
    const float* Wa  = (const float*)d_in[wb + 10];

    float* out = (float*)d_out;

    k_prep<<<1, 128>>>(Wq, Wk, Wew, bq, bk, bew, Wa);
    k_zero_small<<<(BN + 255) / 256, 256>>>();
    k_node<<<BN / 8, 256>>>(x);
    k_edge1<<<(EE * 4) / 128, 128>>>(ei, bi, e_emb);
    k_scanA<<<SCAN_NBLK, SCAN_B>>>();
    k_scanB<<<1, SCAN_B>>>();
    k_scanC<<<SCAN_NBLK, SCAN_B>>>();
    k_scatter<<<(EE + 255) / 256, 256>>>(ei, bi);
    k_gather<<<BN / 8, 256>>>(x, e_emb);
    k_epi<<<BN / NPB, 128>>>(Wv, bv, Wev, bev, out);
    (void)out_size;
}

// round 7
// speedup vs baseline: 1.4253x; 1.0603x over previous
#include <cuda_runtime.h>
#include <cuda_bf16.h>
#include <math.h>

#define BB 4
#define NN 50000
#define BN 200000          // BB*NN
#define EE 600000
#define DD 128
#define DE 64
#define NPB 16             // nodes per epilogue block
#define SCAN_B 512
#define SCAN_NBLK ((BN + SCAN_B - 1) / SCAN_B)   // 391

// ---- scratch: static __device__ arrays only ----
__device__ float4 g_y4[(size_t)BN * 32];   // Σ alpha * x[dst]  per src (102.4 MB)
__device__ float4 g_u4[(size_t)BN * 16];   // Σ alpha * e_emb   per src (51.2 MB)
__device__ float  g_asum[BN];              // Σ alpha           per src
__device__ float  g_attsum[BN];            // Σ exp(logit)      per dst
__device__ float  g_attexp[EE];
__device__ float  g_qa[BN];
__device__ float  g_ka[BN];
__device__ float4 g_wqa4[32];
__device__ float4 g_wka4[32];
__device__ float4 g_wea4[16];
__device__ float  g_cb[1];
// CSR build
__device__ unsigned g_cnt[BN];             // degree histogram (by src)
__device__ unsigned g_off[BN];             // exclusive offsets
__device__ unsigned g_cur[BN];             // scatter cursors
__device__ unsigned g_bsum[SCAN_NBLK];
__device__ unsigned g_boff[SCAN_NBLK];
__device__ int4     g_meta[EE];            // sorted-by-src: {gd, eid, alpha_bits, 0}

__device__ __forceinline__ void redg(float* p, float v) {
    unsigned long long gp = (unsigned long long)__cvta_generic_to_global(p);
    asm volatile("red.global.add.f32 [%0], %1;" :: "l"(gp), "f"(v) : "memory");
}
__device__ __forceinline__ void redgu(unsigned* p, unsigned v) {
    unsigned long long gp = (unsigned long long)__cvta_generic_to_global(p);
    asm volatile("red.global.add.u32 [%0], %1;" :: "l"(gp), "r"(v) : "memory");
}
__device__ __forceinline__ unsigned long long pk2(float x) {
    unsigned long long r;
    asm("mov.b64 %0, {%1, %1};" : "=l"(r) : "f"(x));
    return r;
}
__device__ __forceinline__ void ffma2(unsigned long long& d, unsigned long long a,
                                      unsigned long long b) {
    asm("fma.rn.f32x2 %0, %1, %2, %0;" : "+l"(d) : "l"(a), "l"(b));
}

// ---------------------------------------------------------------------------
__global__ void k_prep(const float* __restrict__ Wq, const float* __restrict__ Wk,
                       const float* __restrict__ Wew,
                       const float* __restrict__ bq, const float* __restrict__ bk,
                       const float* __restrict__ bew, const float* __restrict__ Wa) {
    int j = threadIdx.x;
    float aq = 0.f, ak = 0.f;
    for (int k = 0; k < DD; k++) {
        float wa = Wa[k];
        aq += Wq[j * DD + k] * wa;
        ak += Wk[j * DD + k] * wa;
    }
    ((float*)g_wqa4)[j] = aq;
    ((float*)g_wka4)[j] = ak;
    if (j < DE) {
        float ae = 0.f;
        for (int k = 0; k < DD; k++) ae += Wew[j * DD + k] * Wa[k];
        ((float*)g_wea4)[j] = ae;
    }
    if (j == 0) {
        float c = 0.f;
        for (int k = 0; k < DD; k++) c += (bq[k] + bk[k] + bew[k]) * Wa[k];
        g_cb[0] = c;
    }
}

__global__ void k_zero_small() {
    int i = blockIdx.x * blockDim.x + threadIdx.x;
    if (i < BN) { g_attsum[i] = 0.f; g_cnt[i] = 0u; g_cur[i] = 0u; }
}

// ---------------------------------------------------------------------------
__global__ __launch_bounds__(256) void k_node(const float* __restrict__ x) {
    int w = (int)((blockIdx.x * blockDim.x + threadIdx.x) >> 5);
    int lane = threadIdx.x & 31;
    if (w >= BN) return;
    float4 xv = ((const float4*)x)[(size_t)w * 32 + lane];
    float4 wq = g_wqa4[lane];
    float4 wk = g_wka4[lane];
    float pq = xv.x * wq.x + xv.y * wq.y + xv.z * wq.z + xv.w * wq.w;
    float pk = xv.x * wk.x + xv.y * wk.y + xv.z * wk.z + xv.w * wk.w;
    #pragma unroll
    for (int o = 16; o > 0; o >>= 1) {
        pq += __shfl_xor_sync(0xffffffffu, pq, o);
        pk += __shfl_xor_sync(0xffffffffu, pk, o);
    }
    if (lane == 0) { g_qa[w] = pq; g_ka[w] = pk; }
}

// ---------------------------------------------------------------------------
// edge pass 1: logit/exp + attsum red + src-degree histogram
// ---------------------------------------------------------------------------
__global__ __launch_bounds__(128) void k_edge1(const int* __restrict__ ei,
                                               const int* __restrict__ bi,
                                               const float* __restrict__ e_emb) {
    int t = blockIdx.x * blockDim.x + threadIdx.x;
    int e = t >> 2;
    int sub = t & 3;
    if (e >= EE) return;
    const float4* er = (const float4*)(e_emb + (size_t)e * DE);
    float p = 0.f;
    #pragma unroll
    for (int i = 0; i < 4; i++) {
        float4 v  = er[sub * 4 + i];
        float4 wv = g_wea4[sub * 4 + i];
        p += v.x * wv.x + v.y * wv.y + v.z * wv.z + v.w * wv.w;
    }
    p += __shfl_xor_sync(0xffffffffu, p, 1);
    p += __shfl_xor_sync(0xffffffffu, p, 2);
    if (sub == 0) {
        int s = ei[e];
        int d = ei[EE + e];
        int b = bi[e];
        int gs = b * NN + s;
        int gd = b * NN + d;
        float logit = (g_qa[gs] + g_ka[gd] + p + g_cb[0]) * 0.25f;
        float ex = expf(logit);
        g_attexp[e] = ex;
        redg(&g_attsum[gd], ex);
        redgu(&g_cnt[gs], 1u);
    }
}

// ---------------------------------------------------------------------------
// 3-kernel exclusive scan of g_cnt -> g_off
// ---------------------------------------------------------------------------
__global__ void k_scanA() {
    __shared__ unsigned sh[SCAN_B];
    int i = blockIdx.x * SCAN_B + threadIdx.x;
    unsigned v = (i < BN) ? g_cnt[i] : 0u;
    sh[threadIdx.x] = v;
    __syncthreads();
    for (int o = 1; o < SCAN_B; o <<= 1) {
        unsigned t = (threadIdx.x >= o) ? sh[threadIdx.x - o] : 0u;
        __syncthreads();
        sh[threadIdx.x] += t;
        __syncthreads();
    }
    if (i < BN) g_off[i] = sh[threadIdx.x] - v;
    if (threadIdx.x == SCAN_B - 1) g_bsum[blockIdx.x] = sh[SCAN_B - 1];
}
__global__ void k_scanB() {
    __shared__ unsigned sh[SCAN_B];
    int i = threadIdx.x;
    unsigned v = (i < SCAN_NBLK) ? g_bsum[i] : 0u;
    sh[i] = v;
    __syncthreads();
    for (int o = 1; o < SCAN_B; o <<= 1) {
        unsigned t = (i >= o) ? sh[i - o] : 0u;
        __syncthreads();
        sh[i] += t;
        __syncthreads();
    }
    if (i < SCAN_NBLK) g_boff[i] = sh[i] - v;
}
__global__ void k_scanC() {
    int i = blockIdx.x * SCAN_B + threadIdx.x;
    if (i < BN) g_off[i] += g_boff[blockIdx.x];
}

// ---------------------------------------------------------------------------
// scatter edges into src-sorted buckets; one packed STG.128 per edge
// ---------------------------------------------------------------------------
__global__ __launch_bounds__(256) void k_scatter(const int* __restrict__ ei,
                                                 const int* __restrict__ bi) {
    int e = blockIdx.x * blockDim.x + threadIdx.x;
    if (e >= EE) return;
    int s = ei[e];
    int d = ei[EE + e];
    int b = bi[e];
    int gs = b * NN + s;
    int gd = b * NN + d;
    float a = g_attexp[e] / (g_attsum[gd] + 1e-9f);
    unsigned pos = g_off[gs] + atomicAdd(&g_cur[gs], 1u);
    g_meta[pos] = make_int4(gd, e, __float_as_int(a), 0);
}

// ---------------------------------------------------------------------------
// gather: one warp per src node. Batch-of-4 predicated edges -> MLP ~8.
// Inactive slots: gd=0/e=0/a=0 (valid address, zero contribution, no branch).
// ---------------------------------------------------------------------------
__global__ __launch_bounds__(256) void k_gather(const float* __restrict__ x,
                                                const float* __restrict__ e_emb) {
    int gs = (int)((blockIdx.x * blockDim.x + threadIdx.x) >> 5);
    int lane = threadIdx.x & 31;
    if (gs >= BN) return;
    unsigned off = g_off[gs];
    unsigned end = off + g_cnt[gs];

    float4 ya = make_float4(0.f, 0.f, 0.f, 0.f);
    float4 ua = make_float4(0.f, 0.f, 0.f, 0.f);
    float asum = 0.f;
    const int4 mz = make_int4(0, 0, 0, 0);

    for (unsigned p = off; p < end; p += 4) {
        int4 m0 = g_meta[p];
        int4 m1 = (p + 1 < end) ? g_meta[p + 1] : mz;
        int4 m2 = (p + 2 < end) ? g_meta[p + 2] : mz;
        int4 m3 = (p + 3 < end) ? g_meta[p + 3] : mz;
        float a0 = __int_as_float(m0.z);
        float a1 = __int_as_float(m1.z);
        float a2 = __int_as_float(m2.z);
        float a3 = __int_as_float(m3.z);

        float4 x0 = ((const float4*)x)[(size_t)m0.x * 32 + lane];
        float4 x1 = ((const float4*)x)[(size_t)m1.x * 32 + lane];
        float4 x2 = ((const float4*)x)[(size_t)m2.x * 32 + lane];
        float4 x3 = ((const float4*)x)[(size_t)m3.x * 32 + lane];

        if (lane < 16) {
            float4 e0 = ((const float4*)e_emb)[(size_t)m0.y * 16 + lane];
            float4 e1 = ((const float4*)e_emb)[(size_t)m1.y * 16 + lane];
            float4 e2 = ((const float4*)e_emb)[(size_t)m2.y * 16 + lane];
            float4 e3 = ((const float4*)e_emb)[(size_t)m3.y * 16 + lane];
            ua.x += a0 * e0.x + a1 * e1.x + a2 * e2.x + a3 * e3.x;
            ua.y += a0 * e0.y + a1 * e1.y + a2 * e2.y + a3 * e3.y;
            ua.z += a0 * e0.z + a1 * e1.z + a2 * e2.z + a3 * e3.z;
            ua.w += a0 * e0.w + a1 * e1.w + a2 * e2.w + a3 * e3.w;
        }

        ya.x += a0 * x0.x + a1 * x1.x + a2 * x2.x + a3 * x3.x;
        ya.y += a0 * x0.y + a1 * x1.y + a2 * x2.y + a3 * x3.y;
        ya.z += a0 * x0.z + a1 * x1.z + a2 * x2.z + a3 * x3.z;
        ya.w += a0 * x0.w + a1 * x1.w + a2 * x2.w + a3 * x3.w;
        asum += a0 + a1 + a2 + a3;
    }
    g_y4[(size_t)gs * 32 + lane] = ya;
    if (lane < 16) g_u4[(size_t)gs * 16 + lane] = ua;
    if (lane == 0) g_asum[gs] = asum;
}

// ---------------------------------------------------------------------------
// epilogue — NPB=16 nodes / 128-thread block; transposed smem + f32x2 FMA
// ---------------------------------------------------------------------------
__global__ __launch_bounds__(128) void k_epi(const float* __restrict__ Wv,
                                             const float* __restrict__ bv,
                                             const float* __restrict__ Wev,
                                             const float* __restrict__ bev,
                                             float* __restrict__ out) {
    __shared__ __align__(16) float yq[(DD + DE) * NPB];
    __shared__ float as[NPB];
    int t = threadIdx.x;
    int n0 = blockIdx.x * NPB;

    {
        int i = t & 15, g = t >> 4;
        const float4* yrow = g_y4 + (size_t)(n0 + i) * 32 + g * 4;
        #pragma unroll
        for (int q = 0; q < 4; q++) {
            float4 v = yrow[q];
            int j = g * 16 + q * 4;
            yq[(j + 0) * NPB + i] = v.x;
            yq[(j + 1) * NPB + i] = v.y;
            yq[(j + 2) * NPB + i] = v.z;
            yq[(j + 3) * NPB + i] = v.w;
        }
        const float4* urow = g_u4 + (size_t)(n0 + i) * 16 + g * 2;
        #pragma unroll
        for (int q = 0; q < 2; q++) {
            float4 v = urow[q];
            int j = DD + g * 8 + q * 4;
            yq[(j + 0) * NPB + i] = v.x;
            yq[(j + 1) * NPB + i] = v.y;
            yq[(j + 2) * NPB + i] = v.z;
            yq[(j + 3) * NPB + i] = v.w;
        }
        if (t < NPB) as[t] = g_asum[n0 + t];
    }
    __syncthreads();

    int c = t;
    unsigned long long acc[8] = {0, 0, 0, 0, 0, 0, 0, 0};

    #pragma unroll 4
    for (int j = 0; j < DD; j++) {
        unsigned long long w2 = pk2(Wv[j * DD + c]);
        const ulonglong2* yr = (const ulonglong2*)(yq + j * NPB);
        ulonglong2 p0 = yr[0], p1 = yr[1], p2 = yr[2], p3 = yr[3];
        ffma2(acc[0], p0.x, w2); ffma2(acc[1], p0.y, w2);
        ffma2(acc[2], p1.x, w2); ffma2(acc[3], p1.y, w2);
        ffma2(acc[4], p2.x, w2); ffma2(acc[5], p2.y, w2);
        ffma2(acc[6], p3.x, w2); ffma2(acc[7], p3.y, w2);
    }
    #pragma unroll 4
    for (int j = 0; j < DE; j++) {
        unsigned long long w2 = pk2(Wev[j * DD + c]);
        const ulonglong2* yr = (const ulonglong2*)(yq + (DD + j) * NPB);
        ulonglong2 p0 = yr[0], p1 = yr[1], p2 = yr[2], p3 = yr[3];
        ffma2(acc[0], p0.x, w2); ffma2(acc[1], p0.y, w2);
        ffma2(acc[2], p1.x, w2); ffma2(acc[3], p1.y, w2);
        ffma2(acc[4], p2.x, w2); ffma2(acc[5], p2.y, w2);
        ffma2(acc[6], p3.x, w2); ffma2(acc[7], p3.y, w2);
    }

    float bb = bv[c] + bev[c];
    #pragma unroll
    for (int m = 0; m < 8; m++) {
        float lo, hi;
        asm("mov.b64 {%0, %1}, %2;" : "=f"(lo), "=f"(hi) : "l"(acc[m]));
        out[(size_t)(n0 + 2 * m + 0) * DD + c] = lo + as[2 * m + 0] * bb;
        out[(size_t)(n0 + 2 * m + 1) * DD + c] = hi + as[2 * m + 1] * bb;
    }
}

// ---------------------------------------------------------------------------
extern "C" void kernel_launch(void* const* d_in, const int* in_sizes, int n_in,
                              void* d_out, int out_size) {
    const float* x     = (const float*)d_in[0];
    const int*   ei    = (const int*)d_in[1];
    const float* e_emb = (const float*)d_in[2];
    const int*   bi    = (const int*)d_in[3];

    int wb = 4;
    if (n_in >= 16 && in_sizes[4] <= 1) wb = 5;
    const float* Wq  = (const float*)d_in[wb + 0];
    const float* bq  = (const float*)d_in[wb + 1];
    const float* Wk  = (const float*)d_in[wb + 2];
    const float* bk  = (const float*)d_in[wb + 3];
    const float* Wv  = (const float*)d_in[wb + 4];
    const float* bv  = (const float*)d_in[wb + 5];
    const float* Wew = (const float*)d_in[wb + 6];
    const float* bew = (const float*)d_in[wb + 7];
    const float* Wev = (const float*)d_in[wb + 8];
    const float* bev = (const float*)d_in[wb + 9];
    const float* Wa  = (const float*)d_in[wb + 10];

    float* out = (float*)d_out;

    k_prep<<<1, 128>>>(Wq, Wk, Wew, bq, bk, bew, Wa);
    k_zero_small<<<(BN + 255) / 256, 256>>>();
    k_node<<<BN / 8, 256>>>(x);
    k_edge1<<<(EE * 4) / 128, 128>>>(ei, bi, e_emb);
    k_scanA<<<SCAN_NBLK, SCAN_B>>>();
    k_scanB<<<1, SCAN_B>>>();
    k_scanC<<<SCAN_NBLK, SCAN_B>>>();
    k_scatter<<<(EE + 255) / 256, 256>>>(ei, bi);
    k_gather<<<BN / 8, 256>>>(x, e_emb);
    k_epi<<<BN / NPB, 128>>>(Wv, bv, Wev, bev, out);
    (void)out_size;
}